// round 1
// baseline (speedup 1.0000x reference)
#include <cuda_runtime.h>
#include <cuda_bf16.h>
#include <stdint.h>

#define BH_TOTAL 64
#define SEQ 4096
#define DIM 64
#define M2_DIM 512

__device__ __nv_bfloat16 g_SKS[(size_t)BH_TOTAL * M2_DIM * DIM];
__device__ __nv_bfloat16 g_STV[(size_t)BH_TOTAL * M2_DIM * DIM];

// ---------- helpers ----------
static __device__ __forceinline__ uint32_t swz(int row, int g) {
    // 128-byte rows, 16-byte granules, SW128-style XOR swizzle
    return (uint32_t)(row * 128 + ((g ^ (row & 7)) << 4));
}

static __device__ __forceinline__ void ldsm_x4(uint32_t& r0, uint32_t& r1, uint32_t& r2,
                                               uint32_t& r3, uint32_t addr) {
    asm volatile("ldmatrix.sync.aligned.m8n8.x4.shared.b16 {%0,%1,%2,%3}, [%4];"
                 : "=r"(r0), "=r"(r1), "=r"(r2), "=r"(r3) : "r"(addr));
}
static __device__ __forceinline__ void ldsm_x4_t(uint32_t& r0, uint32_t& r1, uint32_t& r2,
                                                 uint32_t& r3, uint32_t addr) {
    asm volatile("ldmatrix.sync.aligned.m8n8.x4.trans.shared.b16 {%0,%1,%2,%3}, [%4];"
                 : "=r"(r0), "=r"(r1), "=r"(r2), "=r"(r3) : "r"(addr));
}
static __device__ __forceinline__ void mma_bf16(float* c, uint32_t a0, uint32_t a1,
                                                uint32_t a2, uint32_t a3,
                                                uint32_t b0, uint32_t b1) {
    asm volatile("mma.sync.aligned.m16n8k16.row.col.f32.bf16.bf16.f32 "
                 "{%0,%1,%2,%3}, {%4,%5,%6,%7}, {%8,%9}, {%0,%1,%2,%3};"
                 : "+f"(c[0]), "+f"(c[1]), "+f"(c[2]), "+f"(c[3])
                 : "r"(a0), "r"(a1), "r"(a2), "r"(a3), "r"(b0), "r"(b1));
}
static __device__ __forceinline__ void cp16(uint32_t dst, const void* src) {
    asm volatile("cp.async.cg.shared.global [%0], [%1], 16;" :: "r"(dst), "l"(src));
}
static __device__ __forceinline__ void cp_commit() {
    asm volatile("cp.async.commit_group;");
}
static __device__ __forceinline__ void cp_wait1() {
    asm volatile("cp.async.wait_group 1;");
}
static __device__ __forceinline__ void cp_wait0() {
    asm volatile("cp.async.wait_group 0;");
}
static __device__ __forceinline__ uint32_t packb(float x, float y) {
    __nv_bfloat162 h = __floats2bfloat162_rn(x, y);
    return *reinterpret_cast<uint32_t*>(&h);
}

// ---------- prep: SKS + STV (bf16) ----------
// SKS[bh][m][d2] = (1/8) sum_j K[bh][(m&7)*512 + j*64 + d2][m>>3]
// STV[bh][m][d]  = (1/8) sum_j V[bh][8m+j][d]
__global__ __launch_bounds__(256) void prep_kernel(const float* __restrict__ K,
                                                   const float* __restrict__ V) {
    __shared__ float acc[64][65];
    const int tid = threadIdx.x;
    const int mb = blockIdx.x;   // 0..7
    const int bh = blockIdx.y;   // 0..63

    // --- SKS: accumulate transpose of 512x64 K slab into acc[dk][d2] ---
    const float* Kb = K + ((size_t)bh * SEQ + (size_t)mb * 512) * DIM;
    float a[16];
#pragma unroll
    for (int e = 0; e < 16; e++) a[e] = 0.f;
    for (int j = 0; j < 8; j++) {
#pragma unroll
        for (int e = 0; e < 16; e++) {
            int i = e * 256 + tid;
            int r = i >> 6, c = i & 63;          // r = d2-local, c = dk
            a[e] += Kb[(size_t)(j * 64 + r) * DIM + c];
        }
    }
#pragma unroll
    for (int e = 0; e < 16; e++) {
        int i = e * 256 + tid;
        int r = i >> 6, c = i & 63;
        acc[c][r] = a[e];                         // transposed store (padded, conflict-free)
    }
    __syncthreads();

    __nv_bfloat16* dstS = g_SKS + (size_t)bh * M2_DIM * DIM;
#pragma unroll
    for (int e = 0; e < 16; e++) {
        int i = e * 256 + tid;
        int dk = i >> 6, d2 = i & 63;
        dstS[(size_t)(8 * dk + mb) * DIM + d2] = __float2bfloat16(acc[dk][d2] * 0.125f);
    }

    // --- STV: chunk mean of V, this block does m in [mb*64, mb*64+64) ---
    const float* Vb = V + (size_t)bh * SEQ * DIM;
    __nv_bfloat16* dstV = g_STV + (size_t)bh * M2_DIM * DIM;
#pragma unroll
    for (int e = 0; e < 16; e++) {
        int i = e * 256 + tid;
        int ml = i >> 6, d = i & 63;
        int m = mb * 64 + ml;
        float s = 0.f;
#pragma unroll
        for (int j = 0; j < 8; j++) s += Vb[(size_t)(m * 8 + j) * DIM + d];
        dstV[(size_t)m * DIM + d] = __float2bfloat16(s * 0.125f);
    }
}

// ---------- fused sketch attention ----------
// per block: 128 q-rows of one (bh). 8 warps x 16 rows.
// S = Q(128x64) @ SKS^T -> exp -> O += P @ STV, chunked over m in 4 x 128.
__global__ __launch_bounds__(256) void attn_kernel(const float* __restrict__ Q,
                                                   const float* __restrict__ V,
                                                   float* __restrict__ out) {
    extern __shared__ __align__(16) char smem[];
    const int tid = threadIdx.x;
    const int lane = tid & 31;
    const int warp = tid >> 5;
    const int bh = blockIdx.y;
    const int nblk = blockIdx.x * 128;

    const uint32_t sbase = (uint32_t)__cvta_generic_to_shared(smem);
    const uint32_t SQ  = sbase;               // 16 KB  (Q tile 128x64 bf16)
    const uint32_t KS0 = sbase + 16384;       // 16 KB  chunk buf 0 (SKS 128x64 bf16)
    const uint32_t TV0 = sbase + 32768;       // 16 KB  chunk buf 0 (STV)
    const uint32_t KS1 = sbase + 49152;
    const uint32_t TV1 = sbase + 65536;       // total 80 KB

    const __nv_bfloat16* gKS = g_SKS + (size_t)bh * M2_DIM * DIM;
    const __nv_bfloat16* gTV = g_STV + (size_t)bh * M2_DIM * DIM;

    auto load_chunk = [&](int c, uint32_t ksb, uint32_t tvb) {
        const uint4* srcK = reinterpret_cast<const uint4*>(gKS + (size_t)c * 128 * DIM);
        const uint4* srcV = reinterpret_cast<const uint4*>(gTV + (size_t)c * 128 * DIM);
#pragma unroll
        for (int k = 0; k < 4; k++) {
            int gi = k * 256 + tid;
            int row = gi >> 3, g = gi & 7;
            uint32_t so = swz(row, g);
            cp16(ksb + so, srcK + gi);
            cp16(tvb + so, srcV + gi);
        }
    };

    load_chunk(0, KS0, TV0); cp_commit();
    load_chunk(1, KS1, TV1); cp_commit();

    // Q tile: fp32 gmem -> bf16 swizzled smem
    {
        const float* Qb = Q + ((size_t)bh * SEQ + nblk) * DIM;
#pragma unroll
        for (int k = 0; k < 4; k++) {
            int gi = k * 256 + tid;
            int row = gi >> 3, g = gi & 7;
            const float4* s4 = reinterpret_cast<const float4*>(Qb + (size_t)row * DIM + g * 8);
            float4 f0 = s4[0], f1 = s4[1];
            __nv_bfloat162 p0 = __floats2bfloat162_rn(f0.x, f0.y);
            __nv_bfloat162 p1 = __floats2bfloat162_rn(f0.z, f0.w);
            __nv_bfloat162 p2 = __floats2bfloat162_rn(f1.x, f1.y);
            __nv_bfloat162 p3 = __floats2bfloat162_rn(f1.z, f1.w);
            uint4 u;
            u.x = *reinterpret_cast<uint32_t*>(&p0);
            u.y = *reinterpret_cast<uint32_t*>(&p1);
            u.z = *reinterpret_cast<uint32_t*>(&p2);
            u.w = *reinterpret_cast<uint32_t*>(&p3);
            *reinterpret_cast<uint4*>(smem + swz(row, g)) = u;
        }
    }
    __syncthreads();

    // A-frags for Q: warp covers rows [warp*16, warp*16+16), 4 k-tiles of 16
    uint32_t qa[4][4];
#pragma unroll
    for (int kt = 0; kt < 4; kt++) {
        int row = warp * 16 + ((lane >> 3) & 1) * 8 + (lane & 7);
        int g = 2 * kt + ((lane >> 4) & 1);
        ldsm_x4(qa[kt][0], qa[kt][1], qa[kt][2], qa[kt][3], SQ + swz(row, g));
    }

    float o[8][4];
#pragma unroll
    for (int i = 0; i < 8; i++) { o[i][0] = 0.f; o[i][1] = 0.f; o[i][2] = 0.f; o[i][3] = 0.f; }
    float rs0 = 0.f, rs1 = 0.f;

#pragma unroll
    for (int c = 0; c < 4; c++) {
        if (c < 3) cp_wait1(); else cp_wait0();
        __syncthreads();
        const uint32_t ksb = (c & 1) ? KS1 : KS0;
        const uint32_t tvb = (c & 1) ? TV1 : TV0;

        // ---- S = Q @ SKS_chunk^T : 16 x 128 per warp ----
        float s[16][4];
#pragma unroll
        for (int i = 0; i < 16; i++) { s[i][0] = 0.f; s[i][1] = 0.f; s[i][2] = 0.f; s[i][3] = 0.f; }
#pragma unroll
        for (int kt = 0; kt < 4; kt++) {
#pragma unroll
            for (int np = 0; np < 8; np++) {
                int row = np * 16 + ((lane >> 4) & 1) * 8 + (lane & 7);
                int g = 2 * kt + ((lane >> 3) & 1);
                uint32_t b0, b1, b2, b3;
                ldsm_x4(b0, b1, b2, b3, ksb + swz(row, g));
                mma_bf16(s[2 * np],     qa[kt][0], qa[kt][1], qa[kt][2], qa[kt][3], b0, b1);
                mma_bf16(s[2 * np + 1], qa[kt][0], qa[kt][1], qa[kt][2], qa[kt][3], b2, b3);
            }
        }

        // ---- exp (logits are O(1); no max subtraction needed) + rowsum ----
#pragma unroll
        for (int nt = 0; nt < 16; nt++) {
            float e0 = __expf(s[nt][0] * 0.125f);
            float e1 = __expf(s[nt][1] * 0.125f);
            float e2 = __expf(s[nt][2] * 0.125f);
            float e3 = __expf(s[nt][3] * 0.125f);
            s[nt][0] = e0; s[nt][1] = e1; s[nt][2] = e2; s[nt][3] = e3;
            rs0 += e0 + e1;
            rs1 += e2 + e3;
        }

        // ---- O += P @ STV_chunk : (16x128) x (128x64) ----
#pragma unroll
        for (int kt2 = 0; kt2 < 8; kt2++) {
            uint32_t a0 = packb(s[2 * kt2][0],     s[2 * kt2][1]);
            uint32_t a1 = packb(s[2 * kt2][2],     s[2 * kt2][3]);
            uint32_t a2 = packb(s[2 * kt2 + 1][0], s[2 * kt2 + 1][1]);
            uint32_t a3 = packb(s[2 * kt2 + 1][2], s[2 * kt2 + 1][3]);
#pragma unroll
            for (int nbp = 0; nbp < 4; nbp++) {
                int row = kt2 * 16 + ((lane >> 3) & 1) * 8 + (lane & 7);
                int g = 2 * nbp + ((lane >> 4) & 1);
                uint32_t b0, b1, b2, b3;
                ldsm_x4_t(b0, b1, b2, b3, tvb + swz(row, g));
                mma_bf16(o[2 * nbp],     a0, a1, a2, a3, b0, b1);
                mma_bf16(o[2 * nbp + 1], a0, a1, a2, a3, b2, b3);
            }
        }
        __syncthreads();
        if (c < 2) { load_chunk(c + 2, ksb, tvb); cp_commit(); }
    }

    // ---- epilogue: rowsum reduce, normalize, + V, store ----
    rs0 += __shfl_xor_sync(0xffffffffu, rs0, 1);
    rs0 += __shfl_xor_sync(0xffffffffu, rs0, 2);
    rs1 += __shfl_xor_sync(0xffffffffu, rs1, 1);
    rs1 += __shfl_xor_sync(0xffffffffu, rs1, 2);
    const float inv0 = 1.f / rs0;
    const float inv1 = 1.f / rs1;

    const int r0 = nblk + warp * 16 + (lane >> 2);
    const size_t base = (size_t)bh * SEQ * DIM;
#pragma unroll
    for (int nb = 0; nb < 8; nb++) {
        int col = nb * 8 + (lane & 3) * 2;
        size_t i0 = base + (size_t)r0 * DIM + col;
        float2 v0 = *reinterpret_cast<const float2*>(V + i0);
        float2 w0 = make_float2(o[nb][0] * inv0 + v0.x, o[nb][1] * inv0 + v0.y);
        *reinterpret_cast<float2*>(out + i0) = w0;
        size_t i1 = i0 + 8 * DIM;
        float2 v1 = *reinterpret_cast<const float2*>(V + i1);
        float2 w1 = make_float2(o[nb][2] * inv1 + v1.x, o[nb][3] * inv1 + v1.y);
        *reinterpret_cast<float2*>(out + i1) = w1;
    }
}

// ---------- launch ----------
extern "C" void kernel_launch(void* const* d_in, const int* in_sizes, int n_in,
                              void* d_out, int out_size) {
    const float* Q = (const float*)d_in[0];
    const float* K = (const float*)d_in[1];
    const float* V = (const float*)d_in[2];
    float* out = (float*)d_out;

    cudaFuncSetAttribute(attn_kernel, cudaFuncAttributeMaxDynamicSharedMemorySize, 81920);

    prep_kernel<<<dim3(8, BH_TOTAL), 256>>>(K, V);
    attn_kernel<<<dim3(SEQ / 128, BH_TOTAL), 256, 81920>>>(Q, V, out);
}

// round 2
// speedup vs baseline: 1.1112x; 1.1112x over previous
#include <cuda_runtime.h>
#include <cuda_bf16.h>
#include <stdint.h>

#define BH_TOTAL 64
#define SEQ 4096
#define DIM 64
#define M2_DIM 512

__device__ __nv_bfloat16 g_SKS[(size_t)BH_TOTAL * M2_DIM * DIM];
__device__ __nv_bfloat16 g_STV[(size_t)BH_TOTAL * M2_DIM * DIM];

// ---------- helpers ----------
static __device__ __forceinline__ uint32_t swz(int row, int g) {
    // 128-byte rows, 16-byte granules, SW128-style XOR swizzle
    return (uint32_t)(row * 128 + ((g ^ (row & 7)) << 4));
}

static __device__ __forceinline__ void ldsm_x4(uint32_t& r0, uint32_t& r1, uint32_t& r2,
                                               uint32_t& r3, uint32_t addr) {
    asm volatile("ldmatrix.sync.aligned.m8n8.x4.shared.b16 {%0,%1,%2,%3}, [%4];"
                 : "=r"(r0), "=r"(r1), "=r"(r2), "=r"(r3) : "r"(addr));
}
static __device__ __forceinline__ void ldsm_x4_t(uint32_t& r0, uint32_t& r1, uint32_t& r2,
                                                 uint32_t& r3, uint32_t addr) {
    asm volatile("ldmatrix.sync.aligned.m8n8.x4.trans.shared.b16 {%0,%1,%2,%3}, [%4];"
                 : "=r"(r0), "=r"(r1), "=r"(r2), "=r"(r3) : "r"(addr));
}
static __device__ __forceinline__ void mma_bf16(float* c, uint32_t a0, uint32_t a1,
                                                uint32_t a2, uint32_t a3,
                                                uint32_t b0, uint32_t b1) {
    asm volatile("mma.sync.aligned.m16n8k16.row.col.f32.bf16.bf16.f32 "
                 "{%0,%1,%2,%3}, {%4,%5,%6,%7}, {%8,%9}, {%0,%1,%2,%3};"
                 : "+f"(c[0]), "+f"(c[1]), "+f"(c[2]), "+f"(c[3])
                 : "r"(a0), "r"(a1), "r"(a2), "r"(a3), "r"(b0), "r"(b1));
}
static __device__ __forceinline__ void cp16(uint32_t dst, const void* src) {
    asm volatile("cp.async.cg.shared.global [%0], [%1], 16;" :: "r"(dst), "l"(src));
}
static __device__ __forceinline__ void cp_commit() {
    asm volatile("cp.async.commit_group;");
}
static __device__ __forceinline__ void cp_wait1() {
    asm volatile("cp.async.wait_group 1;");
}
static __device__ __forceinline__ void cp_wait0() {
    asm volatile("cp.async.wait_group 0;");
}
static __device__ __forceinline__ uint32_t packb(float x, float y) {
    __nv_bfloat162 h = __floats2bfloat162_rn(x, y);
    return *reinterpret_cast<uint32_t*>(&h);
}

// ---------- prep: SKS + STV (bf16) ----------
// SKS[bh][m][d2] = (1/8) sum_j K[bh][(m&7)*512 + j*64 + d2][m>>3]
// STV[bh][m][d]  = (1/8) sum_j V[bh][8m+j][d]
__global__ __launch_bounds__(256) void prep_kernel(const float* __restrict__ K,
                                                   const float* __restrict__ V) {
    __shared__ float acc[64][65];
    const int tid = threadIdx.x;
    const int mb = blockIdx.x;   // 0..7
    const int bh = blockIdx.y;   // 0..63

    // --- SKS: accumulate transpose of 512x64 K slab into acc[dk][d2] ---
    const float* Kb = K + ((size_t)bh * SEQ + (size_t)mb * 512) * DIM;
    float a[16];
#pragma unroll
    for (int e = 0; e < 16; e++) a[e] = 0.f;
    for (int j = 0; j < 8; j++) {
#pragma unroll
        for (int e = 0; e < 16; e++) {
            int i = e * 256 + tid;
            int r = i >> 6, c = i & 63;          // r = d2-local, c = dk
            a[e] += Kb[(size_t)(j * 64 + r) * DIM + c];
        }
    }
#pragma unroll
    for (int e = 0; e < 16; e++) {
        int i = e * 256 + tid;
        int r = i >> 6, c = i & 63;
        acc[c][r] = a[e];                         // transposed store (padded, conflict-free)
    }
    __syncthreads();

    __nv_bfloat16* dstS = g_SKS + (size_t)bh * M2_DIM * DIM;
#pragma unroll
    for (int e = 0; e < 16; e++) {
        int i = e * 256 + tid;
        int dk = i >> 6, d2 = i & 63;
        dstS[(size_t)(8 * dk + mb) * DIM + d2] = __float2bfloat16(acc[dk][d2] * 0.125f);
    }

    // --- STV: chunk mean of V, this block does m in [mb*64, mb*64+64) ---
    const float* Vb = V + (size_t)bh * SEQ * DIM;
    __nv_bfloat16* dstV = g_STV + (size_t)bh * M2_DIM * DIM;
#pragma unroll
    for (int e = 0; e < 16; e++) {
        int i = e * 256 + tid;
        int ml = i >> 6, d = i & 63;
        int m = mb * 64 + ml;
        float s = 0.f;
#pragma unroll
        for (int j = 0; j < 8; j++) s += Vb[(size_t)(m * 8 + j) * DIM + d];
        dstV[(size_t)m * DIM + d] = __float2bfloat16(s * 0.125f);
    }
}

// ---------- fused sketch attention ----------
// per block: 128 q-rows of one (bh). 8 warps x 16 rows.
// m chunked 4 x 128 (double-buffered cp.async); each chunk processed in two
// 64-wide n-halves to keep the logits register footprint at 32 regs.
__global__ __launch_bounds__(256, 2) void attn_kernel(const float* __restrict__ Q,
                                                      const float* __restrict__ V,
                                                      float* __restrict__ out) {
    extern __shared__ __align__(16) char smem[];
    const int tid = threadIdx.x;
    const int lane = tid & 31;
    const int warp = tid >> 5;
    const int bh = blockIdx.y;
    const int nblk = blockIdx.x * 128;

    const uint32_t sbase = (uint32_t)__cvta_generic_to_shared(smem);
    const uint32_t SQ  = sbase;               // 16 KB  (Q tile 128x64 bf16)
    const uint32_t KS0 = sbase + 16384;       // 16 KB  chunk buf 0 (SKS 128x64 bf16)
    const uint32_t TV0 = sbase + 32768;       // 16 KB  chunk buf 0 (STV)
    const uint32_t KS1 = sbase + 49152;
    const uint32_t TV1 = sbase + 65536;       // total 80 KB

    const __nv_bfloat16* gKS = g_SKS + (size_t)bh * M2_DIM * DIM;
    const __nv_bfloat16* gTV = g_STV + (size_t)bh * M2_DIM * DIM;

    auto load_chunk = [&](int c, uint32_t ksb, uint32_t tvb) {
        const uint4* srcK = reinterpret_cast<const uint4*>(gKS + (size_t)c * 128 * DIM);
        const uint4* srcV = reinterpret_cast<const uint4*>(gTV + (size_t)c * 128 * DIM);
#pragma unroll
        for (int k = 0; k < 4; k++) {
            int gi = k * 256 + tid;
            int row = gi >> 3, g = gi & 7;
            uint32_t so = swz(row, g);
            cp16(ksb + so, srcK + gi);
            cp16(tvb + so, srcV + gi);
        }
    };

    load_chunk(0, KS0, TV0); cp_commit();
    load_chunk(1, KS1, TV1); cp_commit();

    // Q tile: fp32 gmem -> bf16 swizzled smem
    {
        const float* Qb = Q + ((size_t)bh * SEQ + nblk) * DIM;
#pragma unroll
        for (int k = 0; k < 4; k++) {
            int gi = k * 256 + tid;
            int row = gi >> 3, g = gi & 7;
            const float4* s4 = reinterpret_cast<const float4*>(Qb + (size_t)row * DIM + g * 8);
            float4 f0 = s4[0], f1 = s4[1];
            __nv_bfloat162 p0 = __floats2bfloat162_rn(f0.x, f0.y);
            __nv_bfloat162 p1 = __floats2bfloat162_rn(f0.z, f0.w);
            __nv_bfloat162 p2 = __floats2bfloat162_rn(f1.x, f1.y);
            __nv_bfloat162 p3 = __floats2bfloat162_rn(f1.z, f1.w);
            uint4 u;
            u.x = *reinterpret_cast<uint32_t*>(&p0);
            u.y = *reinterpret_cast<uint32_t*>(&p1);
            u.z = *reinterpret_cast<uint32_t*>(&p2);
            u.w = *reinterpret_cast<uint32_t*>(&p3);
            *reinterpret_cast<uint4*>(smem + swz(row, g)) = u;
        }
    }
    __syncthreads();

    // A-frags for Q: warp covers rows [warp*16, warp*16+16), 4 k-tiles of 16
    uint32_t qa[4][4];
#pragma unroll
    for (int kt = 0; kt < 4; kt++) {
        int row = warp * 16 + ((lane >> 3) & 1) * 8 + (lane & 7);
        int g = 2 * kt + ((lane >> 4) & 1);
        ldsm_x4(qa[kt][0], qa[kt][1], qa[kt][2], qa[kt][3], SQ + swz(row, g));
    }

    float o[8][4];
#pragma unroll
    for (int i = 0; i < 8; i++) { o[i][0] = 0.f; o[i][1] = 0.f; o[i][2] = 0.f; o[i][3] = 0.f; }
    float rs0 = 0.f, rs1 = 0.f;

#pragma unroll
    for (int c = 0; c < 4; c++) {
        if (c < 3) cp_wait1(); else cp_wait0();
        __syncthreads();
        const uint32_t ksb = (c & 1) ? KS1 : KS0;
        const uint32_t tvb = (c & 1) ? TV1 : TV0;

        // two 64-wide n-halves per chunk: keeps live logits at s[8][4]
#pragma unroll
        for (int h = 0; h < 2; h++) {
            // ---- S = Q @ SKS_half^T : 16 x 64 per warp ----
            float s[8][4];
#pragma unroll
            for (int i = 0; i < 8; i++) { s[i][0] = 0.f; s[i][1] = 0.f; s[i][2] = 0.f; s[i][3] = 0.f; }
#pragma unroll
            for (int kt = 0; kt < 4; kt++) {
#pragma unroll
                for (int np = 0; np < 4; np++) {
                    int row = h * 64 + np * 16 + ((lane >> 4) & 1) * 8 + (lane & 7);
                    int g = 2 * kt + ((lane >> 3) & 1);
                    uint32_t b0, b1, b2, b3;
                    ldsm_x4(b0, b1, b2, b3, ksb + swz(row, g));
                    mma_bf16(s[2 * np],     qa[kt][0], qa[kt][1], qa[kt][2], qa[kt][3], b0, b1);
                    mma_bf16(s[2 * np + 1], qa[kt][0], qa[kt][1], qa[kt][2], qa[kt][3], b2, b3);
                }
            }

            // ---- exp (logits O(1); no max subtraction) + rowsum + pack ----
            uint32_t au[4][4];
#pragma unroll
            for (int kt2 = 0; kt2 < 4; kt2++) {
                float e00 = __expf(s[2 * kt2][0] * 0.125f);
                float e01 = __expf(s[2 * kt2][1] * 0.125f);
                float e02 = __expf(s[2 * kt2][2] * 0.125f);
                float e03 = __expf(s[2 * kt2][3] * 0.125f);
                float e10 = __expf(s[2 * kt2 + 1][0] * 0.125f);
                float e11 = __expf(s[2 * kt2 + 1][1] * 0.125f);
                float e12 = __expf(s[2 * kt2 + 1][2] * 0.125f);
                float e13 = __expf(s[2 * kt2 + 1][3] * 0.125f);
                rs0 += e00 + e01 + e10 + e11;
                rs1 += e02 + e03 + e12 + e13;
                au[kt2][0] = packb(e00, e01);
                au[kt2][1] = packb(e02, e03);
                au[kt2][2] = packb(e10, e11);
                au[kt2][3] = packb(e12, e13);
            }

            // ---- O += P_half @ STV_half : (16x64) x (64x64) ----
#pragma unroll
            for (int kt2 = 0; kt2 < 4; kt2++) {
#pragma unroll
                for (int nbp = 0; nbp < 4; nbp++) {
                    int row = h * 64 + kt2 * 16 + ((lane >> 3) & 1) * 8 + (lane & 7);
                    int g = 2 * nbp + ((lane >> 4) & 1);
                    uint32_t b0, b1, b2, b3;
                    ldsm_x4_t(b0, b1, b2, b3, tvb + swz(row, g));
                    mma_bf16(o[2 * nbp],     au[kt2][0], au[kt2][1], au[kt2][2], au[kt2][3], b0, b1);
                    mma_bf16(o[2 * nbp + 1], au[kt2][0], au[kt2][1], au[kt2][2], au[kt2][3], b2, b3);
                }
            }
        }
        __syncthreads();
        if (c < 2) { load_chunk(c + 2, ksb, tvb); cp_commit(); }
    }

    // ---- epilogue: rowsum reduce, normalize, + V, store ----
    rs0 += __shfl_xor_sync(0xffffffffu, rs0, 1);
    rs0 += __shfl_xor_sync(0xffffffffu, rs0, 2);
    rs1 += __shfl_xor_sync(0xffffffffu, rs1, 1);
    rs1 += __shfl_xor_sync(0xffffffffu, rs1, 2);
    const float inv0 = 1.f / rs0;
    const float inv1 = 1.f / rs1;

    const int r0 = nblk + warp * 16 + (lane >> 2);
    const size_t base = (size_t)bh * SEQ * DIM;
#pragma unroll
    for (int nb = 0; nb < 8; nb++) {
        int col = nb * 8 + (lane & 3) * 2;
        size_t i0 = base + (size_t)r0 * DIM + col;
        float2 v0 = *reinterpret_cast<const float2*>(V + i0);
        float2 w0 = make_float2(o[nb][0] * inv0 + v0.x, o[nb][1] * inv0 + v0.y);
        *reinterpret_cast<float2*>(out + i0) = w0;
        size_t i1 = i0 + 8 * DIM;
        float2 v1 = *reinterpret_cast<const float2*>(V + i1);
        float2 w1 = make_float2(o[nb][2] * inv1 + v1.x, o[nb][3] * inv1 + v1.y);
        *reinterpret_cast<float2*>(out + i1) = w1;
    }
}

// ---------- launch ----------
extern "C" void kernel_launch(void* const* d_in, const int* in_sizes, int n_in,
                              void* d_out, int out_size) {
    const float* Q = (const float*)d_in[0];
    const float* K = (const float*)d_in[1];
    const float* V = (const float*)d_in[2];
    float* out = (float*)d_out;

    cudaFuncSetAttribute(attn_kernel, cudaFuncAttributeMaxDynamicSharedMemorySize, 81920);

    prep_kernel<<<dim3(8, BH_TOTAL), 256>>>(K, V);
    attn_kernel<<<dim3(SEQ / 128, BH_TOTAL), 256, 81920>>>(Q, V, out);
}

// round 4
// speedup vs baseline: 1.2237x; 1.1012x over previous
#include <cuda_runtime.h>
#include <cuda_fp16.h>
#include <stdint.h>

#define BH_TOTAL 64
#define SEQ 4096
#define DIM 64
#define M2_DIM 512
#define QROWS 256

// f16 sketches: SKS [bh][m2][d], STV [bh][m2][d]
__device__ __half g_SKS[(size_t)BH_TOTAL * M2_DIM * DIM];
__device__ __half g_STV[(size_t)BH_TOTAL * M2_DIM * DIM];

// ---------- helpers ----------
static __device__ __forceinline__ uint32_t swz(int row, int g) {
    // 128-byte rows, 16-byte granules, XOR swizzle
    return (uint32_t)(row * 128 + ((g ^ (row & 7)) << 4));
}
static __device__ __forceinline__ void ldsm_x4(uint32_t& r0, uint32_t& r1, uint32_t& r2,
                                               uint32_t& r3, uint32_t addr) {
    asm volatile("ldmatrix.sync.aligned.m8n8.x4.shared.b16 {%0,%1,%2,%3}, [%4];"
                 : "=r"(r0), "=r"(r1), "=r"(r2), "=r"(r3) : "r"(addr));
}
static __device__ __forceinline__ void ldsm_x4_t(uint32_t& r0, uint32_t& r1, uint32_t& r2,
                                                 uint32_t& r3, uint32_t addr) {
    asm volatile("ldmatrix.sync.aligned.m8n8.x4.trans.shared.b16 {%0,%1,%2,%3}, [%4];"
                 : "=r"(r0), "=r"(r1), "=r"(r2), "=r"(r3) : "r"(addr));
}
// f16 x f16 -> f16 accum (C = 2 regs of f16x2)
static __device__ __forceinline__ void mma_f16(uint32_t& c0, uint32_t& c1,
                                               uint32_t a0, uint32_t a1, uint32_t a2, uint32_t a3,
                                               uint32_t b0, uint32_t b1) {
    asm volatile("mma.sync.aligned.m16n8k16.row.col.f16.f16.f16.f16 "
                 "{%0,%1}, {%2,%3,%4,%5}, {%6,%7}, {%0,%1};"
                 : "+r"(c0), "+r"(c1)
                 : "r"(a0), "r"(a1), "r"(a2), "r"(a3), "r"(b0), "r"(b1));
}
static __device__ __forceinline__ void cp16(uint32_t dst, const void* src) {
    asm volatile("cp.async.cg.shared.global [%0], [%1], 16;" :: "r"(dst), "l"(src));
}
#define CP_COMMIT() asm volatile("cp.async.commit_group;")
static __device__ __forceinline__ float ex2(float x) {
    float r;
    asm("ex2.approx.f32 %0, %1;" : "=f"(r) : "f"(x));
    return r;
}
static __device__ __forceinline__ uint32_t packh(float x, float y) {
    __half2 h = __floats2half2_rn(x, y);
    return *reinterpret_cast<uint32_t*>(&h);
}
static __device__ __forceinline__ float2 unpackh(uint32_t u) {
    return __half22float2(*reinterpret_cast<__half2*>(&u));
}

// ---------- prep: SKS + STV (f16) ----------
// SKS[bh][m][d2] = (1/8) sum_j K[bh][(m&7)*512 + j*64 + d2][m>>3]
// STV[bh][m][d]  = (1/8) sum_j V[bh][8m+j][d]
__global__ __launch_bounds__(256) void prep_kernel(const float* __restrict__ K,
                                                   const float* __restrict__ V) {
    __shared__ float acc[64][65];
    const int tid = threadIdx.x;
    const int mb = blockIdx.x;   // 0..7
    const int bh = blockIdx.y;   // 0..63

    // --- SKS: transpose-accumulate 512x64 K slab ---
    const float* Kb = K + ((size_t)bh * SEQ + (size_t)mb * 512) * DIM;
    float a[16];
#pragma unroll
    for (int e = 0; e < 16; e++) a[e] = 0.f;
    for (int j = 0; j < 8; j++) {
#pragma unroll
        for (int e = 0; e < 16; e++) {
            int i = e * 256 + tid;
            int r = i >> 6, c = i & 63;
            a[e] += Kb[(size_t)(j * 64 + r) * DIM + c];
        }
    }
#pragma unroll
    for (int e = 0; e < 16; e++) {
        int i = e * 256 + tid;
        int r = i >> 6, c = i & 63;
        acc[c][r] = a[e];
    }
    __syncthreads();

    __half* dstS = g_SKS + (size_t)bh * M2_DIM * DIM;
#pragma unroll
    for (int e = 0; e < 16; e++) {
        int i = e * 256 + tid;
        int dk = i >> 6, d2 = i & 63;
        dstS[(size_t)(8 * dk + mb) * DIM + d2] = __float2half_rn(acc[dk][d2] * 0.125f);
    }

    // --- STV: chunk mean of V ---
    const float* Vb = V + (size_t)bh * SEQ * DIM;
    __half* dstV = g_STV + (size_t)bh * M2_DIM * DIM;
#pragma unroll
    for (int e = 0; e < 16; e++) {
        int i = e * 256 + tid;
        int ml = i >> 6, d = i & 63;
        int m = mb * 64 + ml;
        float s = 0.f;
#pragma unroll
        for (int j = 0; j < 8; j++) s += Vb[(size_t)(m * 8 + j) * DIM + d];
        dstV[(size_t)m * DIM + d] = __float2half_rn(s * 0.125f);
    }
}

// ---------- fused sketch attention (f16 mma, f16 accumulators) ----------
// 256 q-rows per block, 8 warps, 32 rows/warp (2 groups of 16).
// m chunked 4 x 128 (double-buffered cp.async); each chunk in two 64-wide halves.
__global__ __launch_bounds__(256, 2) void attn_kernel(const float* __restrict__ Q,
                                                      const float* __restrict__ V,
                                                      float* __restrict__ out) {
    extern __shared__ __align__(16) char smem[];
    const int tid = threadIdx.x;
    const int lane = tid & 31;
    const int warp = tid >> 5;
    const int bh = blockIdx.y;
    const int nblk = blockIdx.x * QROWS;

    const uint32_t sbase = (uint32_t)__cvta_generic_to_shared(smem);
    const uint32_t SQ  = sbase;               // 32 KB  Q (256x64 f16, swizzled)
    const uint32_t KS0 = sbase + 32768;       // 16 KB each
    const uint32_t KS1 = sbase + 49152;
    const uint32_t TV0 = sbase + 65536;
    const uint32_t TV1 = sbase + 81920;       // total 96 KB

    const __half* gKS = g_SKS + (size_t)bh * M2_DIM * DIM;
    const __half* gTV = g_STV + (size_t)bh * M2_DIM * DIM;

    auto load_chunk = [&](int c, uint32_t ksb, uint32_t tvb) {
        const uint4* srcK = reinterpret_cast<const uint4*>(gKS + (size_t)c * 128 * DIM);
        const uint4* srcV = reinterpret_cast<const uint4*>(gTV + (size_t)c * 128 * DIM);
#pragma unroll
        for (int k = 0; k < 4; k++) {
            int gi = k * 256 + tid;
            int row = gi >> 3, g = gi & 7;
            uint32_t so = swz(row, g);
            cp16(ksb + so, srcK + gi);
            cp16(tvb + so, srcV + gi);
        }
    };

    load_chunk(0, KS0, TV0); CP_COMMIT();
    load_chunk(1, KS1, TV1); CP_COMMIT();

    // Q tile: fp32 -> f16, scale folded: 0.125 * log2(e)
    {
        const float qs = 0.125f * 1.44269504f;
        const float* Qb = Q + ((size_t)bh * SEQ + nblk) * DIM;
#pragma unroll
        for (int k = 0; k < 8; k++) {
            int gi = k * 256 + tid;
            int row = gi >> 3, g = gi & 7;
            const float4* s4 = reinterpret_cast<const float4*>(Qb + (size_t)row * DIM + g * 8);
            float4 f0 = s4[0], f1 = s4[1];
            uint4 u;
            u.x = packh(f0.x * qs, f0.y * qs);
            u.y = packh(f0.z * qs, f0.w * qs);
            u.z = packh(f1.x * qs, f1.y * qs);
            u.w = packh(f1.z * qs, f1.w * qs);
            *reinterpret_cast<uint4*>(smem + swz(row, g)) = u;
        }
    }
    __syncthreads();

    // Q A-frags: warp covers rows [warp*32, warp*32+32): 2 groups x 4 k-tiles
    uint32_t qa[2][4][4];
#pragma unroll
    for (int grp = 0; grp < 2; grp++) {
#pragma unroll
        for (int kt = 0; kt < 4; kt++) {
            int row = warp * 32 + grp * 16 + ((lane >> 3) & 1) * 8 + (lane & 7);
            int g = 2 * kt + ((lane >> 4) & 1);
            ldsm_x4(qa[grp][kt][0], qa[grp][kt][1], qa[grp][kt][2], qa[grp][kt][3],
                    SQ + swz(row, g));
        }
    }

    uint32_t o[2][8][2];
#pragma unroll
    for (int grp = 0; grp < 2; grp++)
#pragma unroll
        for (int t = 0; t < 8; t++) { o[grp][t][0] = 0u; o[grp][t][1] = 0u; }
    float rs[2][2] = {{0.f, 0.f}, {0.f, 0.f}};

#pragma unroll
    for (int c = 0; c < 4; c++) {
        if (c < 3) asm volatile("cp.async.wait_group 1;");
        else       asm volatile("cp.async.wait_group 0;");
        __syncthreads();
        const uint32_t ksb = (c & 1) ? KS1 : KS0;
        const uint32_t tvb = (c & 1) ? TV1 : TV0;

#pragma unroll
        for (int h = 0; h < 2; h++) {
            // ---- S = Q @ SKS_half^T : 32 x 64 per warp, f16 accum ----
            uint32_t s[2][8][2];
#pragma unroll
            for (int grp = 0; grp < 2; grp++)
#pragma unroll
                for (int t = 0; t < 8; t++) { s[grp][t][0] = 0u; s[grp][t][1] = 0u; }

#pragma unroll
            for (int kt = 0; kt < 4; kt++) {
#pragma unroll
                for (int np = 0; np < 4; np++) {
                    int row = h * 64 + np * 16 + ((lane >> 4) & 1) * 8 + (lane & 7);
                    int g = 2 * kt + ((lane >> 3) & 1);
                    uint32_t b0, b1, b2, b3;
                    ldsm_x4(b0, b1, b2, b3, ksb + swz(row, g));
#pragma unroll
                    for (int grp = 0; grp < 2; grp++) {
                        mma_f16(s[grp][2 * np][0],     s[grp][2 * np][1],
                                qa[grp][kt][0], qa[grp][kt][1], qa[grp][kt][2], qa[grp][kt][3],
                                b0, b1);
                        mma_f16(s[grp][2 * np + 1][0], s[grp][2 * np + 1][1],
                                qa[grp][kt][0], qa[grp][kt][1], qa[grp][kt][2], qa[grp][kt][3],
                                b2, b3);
                    }
                }
            }

            // ---- exp2 on S (logits already in log2 domain) + rowsum; in-place to f16 ----
#pragma unroll
            for (int grp = 0; grp < 2; grp++) {
#pragma unroll
                for (int t = 0; t < 8; t++) {
                    float2 v0 = unpackh(s[grp][t][0]);
                    float2 v1 = unpackh(s[grp][t][1]);
                    float e00 = ex2(v0.x), e01 = ex2(v0.y);
                    float e10 = ex2(v1.x), e11 = ex2(v1.y);
                    rs[grp][0] += e00 + e01;
                    rs[grp][1] += e10 + e11;
                    s[grp][t][0] = packh(e00, e01);
                    s[grp][t][1] = packh(e10, e11);
                }
            }

            // ---- O += P_half @ STV_half : A-frags come straight from s regs ----
#pragma unroll
            for (int kt2 = 0; kt2 < 4; kt2++) {
#pragma unroll
                for (int nbp = 0; nbp < 4; nbp++) {
                    int row = h * 64 + kt2 * 16 + ((lane >> 3) & 1) * 8 + (lane & 7);
                    int g = 2 * nbp + ((lane >> 4) & 1);
                    uint32_t b0, b1, b2, b3;
                    ldsm_x4_t(b0, b1, b2, b3, tvb + swz(row, g));
#pragma unroll
                    for (int grp = 0; grp < 2; grp++) {
                        mma_f16(o[grp][2 * nbp][0],     o[grp][2 * nbp][1],
                                s[grp][2 * kt2][0], s[grp][2 * kt2][1],
                                s[grp][2 * kt2 + 1][0], s[grp][2 * kt2 + 1][1],
                                b0, b1);
                        mma_f16(o[grp][2 * nbp + 1][0], o[grp][2 * nbp + 1][1],
                                s[grp][2 * kt2][0], s[grp][2 * kt2][1],
                                s[grp][2 * kt2 + 1][0], s[grp][2 * kt2 + 1][1],
                                b2, b3);
                    }
                }
            }
        }
        __syncthreads();
        if (c < 2) { load_chunk(c + 2, ksb, tvb); CP_COMMIT(); }
    }

    // ---- epilogue: rowsum reduce over lane quads, normalize, + V, store ----
#pragma unroll
    for (int grp = 0; grp < 2; grp++) {
#pragma unroll
        for (int rr = 0; rr < 2; rr++) {
            rs[grp][rr] += __shfl_xor_sync(0xffffffffu, rs[grp][rr], 1);
            rs[grp][rr] += __shfl_xor_sync(0xffffffffu, rs[grp][rr], 2);
        }
    }

    const size_t base = (size_t)bh * SEQ * DIM;
#pragma unroll
    for (int grp = 0; grp < 2; grp++) {
        const float inv0 = 1.f / rs[grp][0];
        const float inv1 = 1.f / rs[grp][1];
        const int row0 = nblk + warp * 32 + grp * 16 + (lane >> 2);
#pragma unroll
        for (int t = 0; t < 8; t++) {
            int col = t * 8 + 2 * (lane & 3);
            size_t i0 = base + (size_t)row0 * DIM + col;
            float2 p0 = unpackh(o[grp][t][0]);
            float2 v0 = *reinterpret_cast<const float2*>(V + i0);
            float2 w0 = make_float2(p0.x * inv0 + v0.x, p0.y * inv0 + v0.y);
            *reinterpret_cast<float2*>(out + i0) = w0;
            size_t i1 = i0 + 8 * DIM;
            float2 p1 = unpackh(o[grp][t][1]);
            float2 v1 = *reinterpret_cast<const float2*>(V + i1);
            float2 w1 = make_float2(p1.x * inv1 + v1.x, p1.y * inv1 + v1.y);
            *reinterpret_cast<float2*>(out + i1) = w1;
        }
    }
}

// ---------- launch ----------
extern "C" void kernel_launch(void* const* d_in, const int* in_sizes, int n_in,
                              void* d_out, int out_size) {
    const float* Q = (const float*)d_in[0];
    const float* K = (const float*)d_in[1];
    const float* V = (const float*)d_in[2];
    float* out = (float*)d_out;

    cudaFuncSetAttribute(attn_kernel, cudaFuncAttributeMaxDynamicSharedMemorySize, 98304);

    prep_kernel<<<dim3(8, BH_TOTAL), 256>>>(K, V);
    attn_kernel<<<dim3(SEQ / QROWS, BH_TOTAL), 256, 98304>>>(Q, V, out);
}